// round 4
// baseline (speedup 1.0000x reference)
#include <cuda_runtime.h>
#include <cuda_bf16.h>
#include <math_constants.h>

// Problem constants (fixed by setup_inputs)
#define BB 2
#define HH 12
#define SS 2048
#define DD 64
#define BH (BB*HH)            // 24
#define NROWS (BB*HH*SS)      // 49152

// Scratch: normalized Q, K, and mask-premultiplied V
__device__ float g_qn[(size_t)NROWS * DD];
__device__ float g_kn[(size_t)NROWS * DD];
__device__ float g_vm[(size_t)NROWS * DD];

// ---------------------------------------------------------------------------
// packed f32x2 helpers
// ---------------------------------------------------------------------------
typedef unsigned long long ull;

__device__ __forceinline__ void ffma2(ull& d, ull a, ull b)
{
    asm("fma.rn.f32x2 %0, %1, %2, %3;" : "=l"(d) : "l"(a), "l"(b), "l"(d));
}
__device__ __forceinline__ ull pack2(float lo, float hi)
{
    ull r;
    asm("mov.b64 %0, {%1, %2};" : "=l"(r) : "f"(lo), "f"(hi));
    return r;
}
__device__ __forceinline__ void unpack2(ull v, float& lo, float& hi)
{
    asm("mov.b64 {%0, %1}, %2;" : "=f"(lo), "=f"(hi) : "l"(v));
}

// ---------------------------------------------------------------------------
// Prep kernel: qn = l2norm(Q) rows, kn = l2norm(K) rows, vm = V * mask
// ---------------------------------------------------------------------------
__global__ void __launch_bounds__(256) yoso_prep(
    const float* __restrict__ Q, const float* __restrict__ K,
    const float* __restrict__ V, const float* __restrict__ mask)
{
    int r = blockIdx.x * 8 + threadIdx.y;
    if (r >= NROWS) return;
    int lane = threadIdx.x;
    int s = r % SS;
    int b = r / (HH * SS);
    float m = mask[b * SS + s];
    size_t off = (size_t)r * DD;

    {
        float2 v = *(const float2*)(Q + off + lane * 2);
        float ss = v.x * v.x + v.y * v.y;
        ss += __shfl_xor_sync(0xffffffff, ss, 16);
        ss += __shfl_xor_sync(0xffffffff, ss, 8);
        ss += __shfl_xor_sync(0xffffffff, ss, 4);
        ss += __shfl_xor_sync(0xffffffff, ss, 2);
        ss += __shfl_xor_sync(0xffffffff, ss, 1);
        float inv = 1.0f / fmaxf(sqrtf(ss), 1e-12f);
        float2 o; o.x = v.x * inv; o.y = v.y * inv;
        *(float2*)(g_qn + off + lane * 2) = o;
    }
    {
        float2 v = *(const float2*)(K + off + lane * 2);
        float ss = v.x * v.x + v.y * v.y;
        ss += __shfl_xor_sync(0xffffffff, ss, 16);
        ss += __shfl_xor_sync(0xffffffff, ss, 8);
        ss += __shfl_xor_sync(0xffffffff, ss, 4);
        ss += __shfl_xor_sync(0xffffffff, ss, 2);
        ss += __shfl_xor_sync(0xffffffff, ss, 1);
        float inv = 1.0f / fmaxf(sqrtf(ss), 1e-12f);
        float2 o; o.x = v.x * inv; o.y = v.y * inv;
        *(float2*)(g_kn + off + lane * 2) = o;
    }
    {
        float2 v = *(const float2*)(V + off + lane * 2);
        float2 o; o.x = v.x * m; o.y = v.y * m;
        *(float2*)(g_vm + off + lane * 2) = o;
    }
}

// ---------------------------------------------------------------------------
// Fast branchless W(x) = (1 - acos(x)/pi)^8
// ---------------------------------------------------------------------------
__device__ __forceinline__ float yoso_w(float x)
{
    x = fminf(fmaxf(x, -1.0f), 1.0f);
    float ax = fabsf(x);
    float p = -0.0012624911f;
    p = fmaf(p, ax,  0.0066700901f);
    p = fmaf(p, ax, -0.0170881256f);
    p = fmaf(p, ax,  0.0308918810f);
    p = fmaf(p, ax, -0.0501743046f);
    p = fmaf(p, ax,  0.0889789874f);
    p = fmaf(p, ax, -0.2145988016f);
    p = fmaf(p, ax,  1.5707963050f);
    float s;
    asm("sqrt.approx.f32 %0, %1;" : "=f"(s) : "f"(1.0f - ax));
    float u = s * p * 0.31830988618379067f;
    float t = (x >= 0.0f) ? (1.0f - u) : u;
    float t2 = t * t;
    float t4 = t2 * t2;
    return t4 * t4;
}

// ---------------------------------------------------------------------------
// Main kernel: 128 query rows per block, 64-key tiles, 256 threads.
// Thread tile 8 rows x 4 cols, packed f32x2 FMAs.
// Software pipelined: K prefetched in regs across GEMM1, V across GEMM2.
// Only 2 __syncthreads per iteration; zero exposed global-load latency.
// ---------------------------------------------------------------------------
#define RS 132
#define KS 68
#define OFF_QT 0
#define OFF_KT (64 * RS)                  // 8448
#define OFF_WT (OFF_KT + 64 * KS)         // 12800
#define OFF_V  (OFF_WT + 64 * RS)         // 21248
#define SMEM_FLOATS (OFF_V + 64 * 64)     // 25344
#define SMEM_BYTES (SMEM_FLOATS * 4)      // 101376

__global__ void __launch_bounds__(256, 2) yoso_main(
    const float* __restrict__ mask, const float* __restrict__ convw,
    float* __restrict__ out)
{
    extern __shared__ float sm[];
    float* sQT = sm + OFF_QT;
    float* sKT = sm + OFF_KT;
    float* sWT = sm + OFF_WT;
    float* sV  = sm + OFF_V;

    const int tid = threadIdx.x;
    const int tx = tid & 15;
    const int ty = tid >> 4;
    const int bh = blockIdx.y;
    const int h = bh % HH;
    const int b = bh / HH;
    const int row0 = blockIdx.x * 128;
    const size_t base = (size_t)bh * SS * DD;

    const int kcol = tid & 63;        // transpose-gather column
    const int krg  = tid >> 6;        // 0..3

    // ---- prologue ----
    // LDG V_0 into regs (consumed after first sync_top)
    float4 vreg[4];
    {
        const float4* vg = (const float4*)(g_vm + base);
        #pragma unroll
        for (int i = 0; i < 4; ++i) vreg[i] = vg[tid + i * 256];
    }
    // LDG K_0 into regs
    float kreg[16];
    {
        const float* kp = g_kn + base + kcol;
        #pragma unroll
        for (int i = 0; i < 16; ++i)
            kreg[i] = kp[(size_t)(krg * 16 + i) * DD];
    }
    // fill sQT[k][row] (transposed), 128 rows x 64 k
    {
        const float* qp = g_qn + base + (size_t)row0 * DD + kcol;
        #pragma unroll
        for (int i = 0; i < 8; ++i) {
            int r0 = krg * 32 + i * 4;
            float4 v;
            v.x = qp[(size_t)(r0 + 0) * DD];
            v.y = qp[(size_t)(r0 + 1) * DD];
            v.z = qp[(size_t)(r0 + 2) * DD];
            v.w = qp[(size_t)(r0 + 3) * DD];
            *(float4*)&sQT[kcol * RS + r0] = v;
        }
    }
    // store K_0 (fresh smem, no readers yet)
    #pragma unroll
    for (int i = 0; i < 4; ++i)
        *(float4*)&sKT[kcol * KS + krg * 16 + i * 4] =
            make_float4(kreg[4*i], kreg[4*i+1], kreg[4*i+2], kreg[4*i+3]);

    ull acc2[4][4];
    #pragma unroll
    for (int i = 0; i < 4; ++i)
        #pragma unroll
        for (int j = 0; j < 4; ++j) acc2[i][j] = 0ull;

    for (int kt = 0; kt < SS / 64; ++kt) {
        // sync_top: publishes sQT/sKT (kt==0) or sKT(kt) (stored after
        // sync_mid of kt-1); retires GEMM2(kt-1) readers of sV/sWT.
        __syncthreads();

        // store V_kt (prev readers retired by sync_top)
        {
            float4* vs = (float4*)sV;
            #pragma unroll
            for (int i = 0; i < 4; ++i) vs[tid + i * 256] = vreg[i];
        }

        // prefetch K_{kt+1} into regs (latency hidden by GEMM1)
        {
            const int kb = ((kt + 1) & 31) * 64;
            const float* kp = g_kn + base + (size_t)kb * DD + kcol;
            #pragma unroll
            for (int i = 0; i < 16; ++i)
                kreg[i] = kp[(size_t)(krg * 16 + i) * DD];
        }

        // ---- GEMM1: dots (8 rows x 4 keys) ----
        ull d2[4][4];
        #pragma unroll
        for (int i = 0; i < 4; ++i)
            #pragma unroll
            for (int j = 0; j < 4; ++j) d2[i][j] = 0ull;

        #pragma unroll 8
        for (int k = 0; k < 64; ++k) {
            ulonglong2 a01 = *(const ulonglong2*)&sQT[k * RS + ty * 8];
            ulonglong2 a23 = *(const ulonglong2*)&sQT[k * RS + ty * 8 + 4];
            float4 bf = *(const float4*)&sKT[k * KS + tx * 4];
            ull b0 = pack2(bf.x, bf.x);
            ull b1 = pack2(bf.y, bf.y);
            ull b2 = pack2(bf.z, bf.z);
            ull b3 = pack2(bf.w, bf.w);
            ffma2(d2[0][0], a01.x, b0); ffma2(d2[0][1], a01.x, b1);
            ffma2(d2[0][2], a01.x, b2); ffma2(d2[0][3], a01.x, b3);
            ffma2(d2[1][0], a01.y, b0); ffma2(d2[1][1], a01.y, b1);
            ffma2(d2[1][2], a01.y, b2); ffma2(d2[1][3], a01.y, b3);
            ffma2(d2[2][0], a23.x, b0); ffma2(d2[2][1], a23.x, b1);
            ffma2(d2[2][2], a23.x, b2); ffma2(d2[2][3], a23.x, b3);
            ffma2(d2[3][0], a23.y, b0); ffma2(d2[3][1], a23.y, b1);
            ffma2(d2[3][2], a23.y, b2); ffma2(d2[3][3], a23.y, b3);
        }

        // transform + store W transposed (prev readers retired by sync_top)
        #pragma unroll
        for (int j = 0; j < 4; ++j) {
            float w[8];
            #pragma unroll
            for (int i2 = 0; i2 < 4; ++i2) {
                float lo, hi;
                unpack2(d2[i2][j], lo, hi);
                w[2 * i2]     = yoso_w(lo);
                w[2 * i2 + 1] = yoso_w(hi);
            }
            float* wp = &sWT[(tx * 4 + j) * RS + ty * 8];
            *(float4*)wp       = make_float4(w[0], w[1], w[2], w[3]);
            *(float4*)(wp + 4) = make_float4(w[4], w[5], w[6], w[7]);
        }

        // sync_mid: publishes sWT + sV; retires GEMM1(kt) readers of sKT.
        __syncthreads();

        // store K_{kt+1} (readers of K_kt retired; visible after next sync_top)
        #pragma unroll
        for (int i = 0; i < 4; ++i)
            *(float4*)&sKT[kcol * KS + krg * 16 + i * 4] =
                make_float4(kreg[4*i], kreg[4*i+1], kreg[4*i+2], kreg[4*i+3]);

        // prefetch V_{kt+1} into regs (latency hidden by GEMM2)
        {
            const int kb = ((kt + 1) & 31) * 64;
            const float4* vg = (const float4*)(g_vm + base + (size_t)kb * DD);
            #pragma unroll
            for (int i = 0; i < 4; ++i) vreg[i] = vg[tid + i * 256];
        }

        // ---- GEMM2: acc += W @ V ----
        #pragma unroll 8
        for (int t = 0; t < 64; ++t) {
            ulonglong2 a01 = *(const ulonglong2*)&sWT[t * RS + ty * 8];
            ulonglong2 a23 = *(const ulonglong2*)&sWT[t * RS + ty * 8 + 4];
            float4 bf = *(const float4*)&sV[t * 64 + tx * 4];
            ull b0 = pack2(bf.x, bf.x);
            ull b1 = pack2(bf.y, bf.y);
            ull b2 = pack2(bf.z, bf.z);
            ull b3 = pack2(bf.w, bf.w);
            ffma2(acc2[0][0], a01.x, b0); ffma2(acc2[0][1], a01.x, b1);
            ffma2(acc2[0][2], a01.x, b2); ffma2(acc2[0][3], a01.x, b3);
            ffma2(acc2[1][0], a01.y, b0); ffma2(acc2[1][1], a01.y, b1);
            ffma2(acc2[1][2], a01.y, b2); ffma2(acc2[1][3], a01.y, b3);
            ffma2(acc2[2][0], a23.x, b0); ffma2(acc2[2][1], a23.x, b1);
            ffma2(acc2[2][2], a23.x, b2); ffma2(acc2[2][3], a23.x, b3);
            ffma2(acc2[3][0], a23.y, b0); ffma2(acc2[3][1], a23.y, b1);
            ffma2(acc2[3][2], a23.y, b2); ffma2(acc2[3][3], a23.y, b3);
        }
    }

    // ---- epilogue: query mask, row l2norm, + conv3(vm) ----
    const float w0 = convw[h * 3 + 0];
    const float w1 = convw[h * 3 + 1];
    const float w2 = convw[h * 3 + 2];

    #pragma unroll
    for (int i = 0; i < 8; ++i) {
        const int gr = row0 + ty * 8 + i;
        const float mq = mask[b * SS + gr];
        float a[4];
        #pragma unroll
        for (int j = 0; j < 4; ++j) {
            float lo, hi;
            unpack2(acc2[i >> 1][j], lo, hi);
            a[j] = ((i & 1) ? hi : lo) * mq;
        }
        float ss = 0.0f;
        #pragma unroll
        for (int j = 0; j < 4; ++j) ss = fmaf(a[j], a[j], ss);
        ss += __shfl_xor_sync(0xffffffff, ss, 1);
        ss += __shfl_xor_sync(0xffffffff, ss, 2);
        ss += __shfl_xor_sync(0xffffffff, ss, 4);
        ss += __shfl_xor_sync(0xffffffff, ss, 8);
        const float inv = 1.0f / fmaxf(sqrtf(ss), 1e-12f);

        const float* vrow = g_vm + base + (size_t)gr * DD + tx * 4;
        float4 c1 = *(const float4*)(vrow);
        float4 c0, c2;
        if (gr > 0)      c0 = *(const float4*)(vrow - DD);
        else             c0 = make_float4(0.f, 0.f, 0.f, 0.f);
        if (gr < SS - 1) c2 = *(const float4*)(vrow + DD);
        else             c2 = make_float4(0.f, 0.f, 0.f, 0.f);

        float4 o;
        o.x = fmaf(a[0], inv, w0 * c0.x + w1 * c1.x + w2 * c2.x);
        o.y = fmaf(a[1], inv, w0 * c0.y + w1 * c1.y + w2 * c2.y);
        o.z = fmaf(a[2], inv, w0 * c0.z + w1 * c1.z + w2 * c2.z);
        o.w = fmaf(a[3], inv, w0 * c0.w + w1 * c1.w + w2 * c2.w);
        *(float4*)&out[base + (size_t)gr * DD + tx * 4] = o;
    }
}

// ---------------------------------------------------------------------------
extern "C" void kernel_launch(void* const* d_in, const int* in_sizes, int n_in,
                              void* d_out, int out_size)
{
    const float* Q     = (const float*)d_in[0];
    const float* K     = (const float*)d_in[1];
    const float* V     = (const float*)d_in[2];
    const float* mask  = (const float*)d_in[3];
    const float* convw = (const float*)d_in[4];
    float* out = (float*)d_out;

    yoso_prep<<<NROWS / 8, dim3(32, 8)>>>(Q, K, V, mask);

    cudaFuncSetAttribute(yoso_main, cudaFuncAttributeMaxDynamicSharedMemorySize,
                         SMEM_BYTES);
    dim3 grid(SS / 128, BH);
    yoso_main<<<grid, 256, SMEM_BYTES>>>(mask, convw, out);
}

// round 7
// speedup vs baseline: 2.0537x; 2.0537x over previous
#include <cuda_runtime.h>
#include <cuda_bf16.h>

#define BB 2
#define HH 12
#define SS 2048
#define DD 64
#define BH 24
#define NROWS 49152

// Scratch: bf16 hi/lo splits of normalized Q/K and masked V; fp32 masked V
__device__ __nv_bfloat16 g_qh[(size_t)NROWS * DD];
__device__ __nv_bfloat16 g_ql[(size_t)NROWS * DD];
__device__ __nv_bfloat16 g_kh[(size_t)NROWS * DD];
__device__ __nv_bfloat16 g_kl[(size_t)NROWS * DD];
__device__ __nv_bfloat16 g_vh[(size_t)NROWS * DD];
__device__ __nv_bfloat16 g_vl[(size_t)NROWS * DD];
__device__ float         g_vm[(size_t)NROWS * DD];

// ---------------------------------------------------------------------------
// helpers
// ---------------------------------------------------------------------------
__device__ __forceinline__ unsigned smem_u32(const void* p)
{
    unsigned a;
    asm("{ .reg .u64 t; cvta.to.shared.u64 t, %1; cvt.u32.u64 %0, t; }"
        : "=r"(a) : "l"(p));
    return a;
}
__device__ __forceinline__ unsigned sw128(unsigned off)
{
    return off ^ ((off >> 3) & 0x70);
}
// pack two f32 into bf16x2 (lo in low half)
__device__ __forceinline__ unsigned pack_bf2(float lo, float hi)
{
    unsigned r;
    asm("cvt.rn.bf16x2.f32 %0, %1, %2;" : "=r"(r) : "f"(hi), "f"(lo));
    return r;
}
__device__ __forceinline__ unsigned pack_resid(float lo, float hi, unsigned hp)
{
    float hl = __uint_as_float(hp << 16);
    float hh = __uint_as_float(hp & 0xFFFF0000u);
    return pack_bf2(lo - hl, hi - hh);
}
__device__ __forceinline__ void ldsm4(unsigned* r, unsigned addr)
{
    asm volatile("ldmatrix.sync.aligned.m8n8.x4.shared.b16 {%0,%1,%2,%3}, [%4];"
                 : "=r"(r[0]), "=r"(r[1]), "=r"(r[2]), "=r"(r[3]) : "r"(addr));
}
__device__ __forceinline__ void ldsm4t(unsigned* r, unsigned addr)
{
    asm volatile("ldmatrix.sync.aligned.m8n8.x4.trans.shared.b16 {%0,%1,%2,%3}, [%4];"
                 : "=r"(r[0]), "=r"(r[1]), "=r"(r[2]), "=r"(r[3]) : "r"(addr));
}
__device__ __forceinline__ void mma16816(float* c, const unsigned* a,
                                         const unsigned* b)
{
    asm volatile(
        "mma.sync.aligned.m16n8k16.row.col.f32.bf16.bf16.f32 "
        "{%0,%1,%2,%3}, {%4,%5,%6,%7}, {%8,%9}, {%0,%1,%2,%3};"
        : "+f"(c[0]), "+f"(c[1]), "+f"(c[2]), "+f"(c[3])
        : "r"(a[0]), "r"(a[1]), "r"(a[2]), "r"(a[3]), "r"(b[0]), "r"(b[1]));
}

// ---------------------------------------------------------------------------
// Prep: l2norm Q,K rows -> bf16 hi/lo; vm = V*mask -> fp32 + bf16 hi/lo
// ---------------------------------------------------------------------------
__global__ void __launch_bounds__(256) yoso_prep(
    const float* __restrict__ Q, const float* __restrict__ K,
    const float* __restrict__ V, const float* __restrict__ mask)
{
    int r = blockIdx.x * 8 + threadIdx.y;
    int lane = threadIdx.x;
    int s = r % SS;
    int b = r / (HH * SS);
    float m = mask[b * SS + s];
    size_t off = (size_t)r * DD;
    size_t uoff = (size_t)r * 32 + lane;

    {
        float2 v = *(const float2*)(Q + off + lane * 2);
        float sq = v.x * v.x + v.y * v.y;
        sq += __shfl_xor_sync(0xffffffff, sq, 16);
        sq += __shfl_xor_sync(0xffffffff, sq, 8);
        sq += __shfl_xor_sync(0xffffffff, sq, 4);
        sq += __shfl_xor_sync(0xffffffff, sq, 2);
        sq += __shfl_xor_sync(0xffffffff, sq, 1);
        float inv = 1.0f / fmaxf(sqrtf(sq), 1e-12f);
        float a0 = v.x * inv;
        float a1 = v.y * inv;
        unsigned hp = pack_bf2(a0, a1);
        ((unsigned*)g_qh)[uoff] = hp;
        ((unsigned*)g_ql)[uoff] = pack_resid(a0, a1, hp);
    }
    {
        float2 v = *(const float2*)(K + off + lane * 2);
        float sq = v.x * v.x + v.y * v.y;
        sq += __shfl_xor_sync(0xffffffff, sq, 16);
        sq += __shfl_xor_sync(0xffffffff, sq, 8);
        sq += __shfl_xor_sync(0xffffffff, sq, 4);
        sq += __shfl_xor_sync(0xffffffff, sq, 2);
        sq += __shfl_xor_sync(0xffffffff, sq, 1);
        float inv = 1.0f / fmaxf(sqrtf(sq), 1e-12f);
        float a0 = v.x * inv;
        float a1 = v.y * inv;
        unsigned hp = pack_bf2(a0, a1);
        ((unsigned*)g_kh)[uoff] = hp;
        ((unsigned*)g_kl)[uoff] = pack_resid(a0, a1, hp);
    }
    {
        float2 v = *(const float2*)(V + off + lane * 2);
        float o0 = v.x * m;
        float o1 = v.y * m;
        float2 o;
        o.x = o0;
        o.y = o1;
        *(float2*)(g_vm + off + lane * 2) = o;
        unsigned hp = pack_bf2(o0, o1);
        ((unsigned*)g_vh)[uoff] = hp;
        ((unsigned*)g_vl)[uoff] = pack_resid(o0, o1, hp);
    }
}

// ---------------------------------------------------------------------------
// Fast branchless W(x) = (1 - acos(x)/pi)^8
// ---------------------------------------------------------------------------
__device__ __forceinline__ float yoso_w(float x)
{
    x = fminf(fmaxf(x, -1.0f), 1.0f);
    float ax = fabsf(x);
    float p = -0.0012624911f;
    p = fmaf(p, ax,  0.0066700901f);
    p = fmaf(p, ax, -0.0170881256f);
    p = fmaf(p, ax,  0.0308918810f);
    p = fmaf(p, ax, -0.0501743046f);
    p = fmaf(p, ax,  0.0889789874f);
    p = fmaf(p, ax, -0.2145988016f);
    p = fmaf(p, ax,  1.5707963050f);
    float s;
    asm("sqrt.approx.f32 %0, %1;" : "=f"(s) : "f"(1.0f - ax));
    float u = s * p * 0.31830988618379067f;
    float t = (x >= 0.0f) ? (1.0f - u) : u;
    float t2 = t * t;
    float t4 = t2 * t2;
    return t4 * t4;
}

// ---------------------------------------------------------------------------
// Main kernel: mma.sync bf16 split GEMMs.
// Block: 128 threads (4 warps), 64 query rows. Warp w owns rows 16w..16w+15.
// Key tiles of 64. W stays in registers (C frag of GEMM1 == A frag of GEMM2).
// ---------------------------------------------------------------------------
#define SM_QH 0
#define SM_QL 8192
#define SM_KH 16384
#define SM_KL 24576
#define SM_VH 32768
#define SM_VL 40960
#define SMEM_BYTES 49152

__device__ __forceinline__ void load_tile64(
    char* dst, const __nv_bfloat16* g, int tid)
{
    #pragma unroll
    for (int i = 0; i < 4; ++i) {
        int c = tid + i * 128;
        int row = c >> 3;
        int col = c & 7;
        uint4 v = *(const uint4*)(g + (size_t)row * DD + col * 8);
        *(uint4*)(dst + sw128((unsigned)(row * 128 + col * 16))) = v;
    }
}

__global__ void __launch_bounds__(128, 3) yoso_mma(
    const float* __restrict__ mask, const float* __restrict__ convw,
    float* __restrict__ out)
{
    extern __shared__ char smc[];
    const int tid = threadIdx.x;
    const int wid = tid >> 5;
    const int lane = tid & 31;
    const int bh = blockIdx.y;
    const int h = bh % HH;
    const int b = bh / HH;
    const int row0 = blockIdx.x * 64;
    const size_t base = (size_t)bh * SS * DD;
    const unsigned smb = smem_u32(smc);

    // Q tiles (persist)
    load_tile64(smc + SM_QH, g_qh + base + (size_t)row0 * DD, tid);
    load_tile64(smc + SM_QL, g_ql + base + (size_t)row0 * DD, tid);

    // ldmatrix lane offsets
    const int mm = lane >> 3;
    const int r8 = lane & 7;
    const unsigned aOff = (unsigned)((16 * wid + (mm & 1) * 8 + r8) * 128
                                     + 16 * (mm >> 1));
    const int kRow = r8 + 8 * (mm >> 1);
    const int kCol = 16 * (mm & 1);
    const int vRow = r8 + 8 * (mm & 1);
    const int vCol = 16 * (mm >> 1);

    float acc[8][4];
    #pragma unroll
    for (int j = 0; j < 8; ++j) {
        #pragma unroll
        for (int i = 0; i < 4; ++i) {
            acc[j][i] = 0.0f;
        }
    }

    for (int kt = 0; kt < SS / 64; ++kt) {
        const int kbase = kt * 64;
        __syncthreads();
        load_tile64(smc + SM_KH, g_kh + base + (size_t)kbase * DD, tid);
        load_tile64(smc + SM_KL, g_kl + base + (size_t)kbase * DD, tid);
        load_tile64(smc + SM_VH, g_vh + base + (size_t)kbase * DD, tid);
        load_tile64(smc + SM_VL, g_vl + base + (size_t)kbase * DD, tid);
        __syncthreads();

        // ---- GEMM1: dots = Q*K^T (3 split products), k = 64 ----
        float dts[8][4];
        #pragma unroll
        for (int j = 0; j < 8; ++j) {
            #pragma unroll
            for (int i = 0; i < 4; ++i) {
                dts[j][i] = 0.0f;
            }
        }
        #pragma unroll
        for (int t = 0; t < 4; ++t) {
            unsigned aH[4];
            unsigned aL[4];
            ldsm4(aH, smb + SM_QH + sw128(aOff + 32 * t));
            ldsm4(aL, smb + SM_QL + sw128(aOff + 32 * t));
            #pragma unroll
            for (int u = 0; u < 4; ++u) {
                unsigned bHf[4];
                unsigned bLf[4];
                unsigned off = sw128((unsigned)((16 * u + kRow) * 128
                                                + 32 * t + kCol));
                ldsm4(bHf, smb + SM_KH + off);
                ldsm4(bLf, smb + SM_KL + off);
                mma16816(dts[2 * u],     aH, bHf);
                mma16816(dts[2 * u + 1], aH, bHf + 2);
                mma16816(dts[2 * u],     aH, bLf);
                mma16816(dts[2 * u + 1], aH, bLf + 2);
                mma16816(dts[2 * u],     aL, bHf);
                mma16816(dts[2 * u + 1], aL, bHf + 2);
            }
        }

        // ---- transform: W = yoso_w(dots), hi/lo bf16 A-fragments ----
        unsigned wh[4][4];
        unsigned wl[4][4];
        #pragma unroll
        for (int t = 0; t < 4; ++t) {
            #pragma unroll
            for (int q2 = 0; q2 < 4; ++q2) {
                int j = 2 * t + (q2 >> 1);
                int g = q2 & 1;
                float f0 = yoso_w(dts[j][2 * g]);
                float f1 = yoso_w(dts[j][2 * g + 1]);
                unsigned hp = pack_bf2(f0, f1);
                wh[t][q2] = hp;
                wl[t][q2] = pack_resid(f0, f1, hp);
            }
        }

        // ---- GEMM2: acc += W * V (3 split products), k = 64 keys ----
        #pragma unroll
        for (int t = 0; t < 4; ++t) {
            #pragma unroll
            for (int u = 0; u < 4; ++u) {
                unsigned vHf[4];
                unsigned vLf[4];
                unsigned off = sw128((unsigned)((16 * t + vRow) * 128
                                                + 32 * u + vCol));
                ldsm4t(vHf, smb + SM_VH + off);
                ldsm4t(vLf, smb + SM_VL + off);
                mma16816(acc[2 * u],     wh[t], vHf);
                mma16816(acc[2 * u + 1], wh[t], vHf + 2);
                mma16816(acc[2 * u],     wh[t], vLf);
                mma16816(acc[2 * u + 1], wh[t], vLf + 2);
                mma16816(acc[2 * u],     wl[t], vHf);
                mma16816(acc[2 * u + 1], wl[t], vHf + 2);
            }
        }
    }

    // ---- epilogue ----
    const int quad = lane >> 2;
    const int qi = lane & 3;
    const int r1 = row0 + 16 * wid + quad;
    const int r2 = r1 + 8;
    const float mq1 = mask[b * SS + r1];
    const float mq2 = mask[b * SS + r2];

    float ss1 = 0.0f;
    float ss2 = 0.0f;
    #pragma unroll
    for (int j = 0; j < 8; ++j) {
        ss1 = fmaf(acc[j][0], acc[j][0], ss1);
        ss1 = fmaf(acc[j][1], acc[j][1], ss1);
        ss2 = fmaf(acc[j][2], acc[j][2], ss2);
        ss2 = fmaf(acc[j][3], acc[j][3], ss2);
    }
    ss1 += __shfl_xor_sync(0xffffffff, ss1, 1);
    ss1 += __shfl_xor_sync(0xffffffff, ss1, 2);
    ss2 += __shfl_xor_sync(0xffffffff, ss2, 1);
    ss2 += __shfl_xor_sync(0xffffffff, ss2, 2);
    const float s1 = mq1 / fmaxf(mq1 * sqrtf(ss1), 1e-12f);
    const float s2 = mq2 / fmaxf(mq2 * sqrtf(ss2), 1e-12f);

    const float w0 = convw[h * 3 + 0];
    const float w1 = convw[h * 3 + 1];
    const float w2 = convw[h * 3 + 2];

    #pragma unroll
    for (int j = 0; j < 8; ++j) {
        const int col = 8 * j + qi * 2;
        {
            const float* vp = g_vm + base + (size_t)r1 * DD + col;
            float2 c1 = *(const float2*)vp;
            float2 c0;
            c0.x = 0.0f;
            c0.y = 0.0f;
            if (r1 > 0) {
                c0 = *(const float2*)(vp - DD);
            }
            float2 c2 = *(const float2*)(vp + DD);   // r1 <= 2039, safe
            float2 o;
            o.x = fmaf(acc[j][0], s1, w0 * c0.x + w1 * c1.x + w2 * c2.x);
            o.y = fmaf(acc[j][1], s1, w0 * c0.y + w1 * c1.y + w2 * c2.y);
            *(float2*)(out + base + (size_t)r1 * DD + col) = o;
        }
        {
            const float* vp = g_vm + base + (size_t)r2 * DD + col;
            float2 c1 = *(const float2*)vp;
            float2 c0 = *(const float2*)(vp - DD);   // r2 >= 8, safe
            float2 c2;
            c2.x = 0.0f;
            c2.y = 0.0f;
            if (r2 < SS - 1) {
                c2 = *(const float2*)(vp + DD);
            }
            float2 o;
            o.x = fmaf(acc[j][2], s2, w0 * c0.x + w1 * c1.x + w2 * c2.x);
            o.y = fmaf(acc[j][3], s2, w0 * c0.y + w1 * c1.y + w2 * c2.y);
            *(float2*)(out + base + (size_t)r2 * DD + col) = o;
        }
    }
}

// ---------------------------------------------------------------------------
extern "C" void kernel_launch(void* const* d_in, const int* in_sizes, int n_in,
                              void* d_out, int out_size)
{
    const float* Q     = (const float*)d_in[0];
    const float* K     = (const float*)d_in[1];
    const float* V     = (const float*)d_in[2];
    const float* mask  = (const float*)d_in[3];
    const float* convw = (const float*)d_in[4];
    float* out = (float*)d_out;

    yoso_prep<<<NROWS / 8, dim3(32, 8)>>>(Q, K, V, mask);

    cudaFuncSetAttribute(yoso_mma, cudaFuncAttributeMaxDynamicSharedMemorySize,
                         SMEM_BYTES);
    dim3 grid(SS / 64, BH);
    yoso_mma<<<grid, 128, SMEM_BYTES>>>(mask, convw, out);
}

// round 8
// speedup vs baseline: 2.3602x; 1.1493x over previous
#include <cuda_runtime.h>
#include <cuda_bf16.h>

#define BB 2
#define HH 12
#define SS 2048
#define DD 64
#define BH 24
#define NROWS 49152

// Scratch: bf16 hi/lo splits of normalized Q/K and masked V; fp32 masked V
__device__ __nv_bfloat16 g_qh[(size_t)NROWS * DD];
__device__ __nv_bfloat16 g_ql[(size_t)NROWS * DD];
__device__ __nv_bfloat16 g_kh[(size_t)NROWS * DD];
__device__ __nv_bfloat16 g_kl[(size_t)NROWS * DD];
__device__ __nv_bfloat16 g_vh[(size_t)NROWS * DD];
__device__ __nv_bfloat16 g_vl[(size_t)NROWS * DD];
__device__ float         g_vm[(size_t)NROWS * DD];

// ---------------------------------------------------------------------------
// helpers
// ---------------------------------------------------------------------------
__device__ __forceinline__ unsigned smem_u32(const void* p)
{
    unsigned a;
    asm("{ .reg .u64 t; cvta.to.shared.u64 t, %1; cvt.u32.u64 %0, t; }"
        : "=r"(a) : "l"(p));
    return a;
}
__device__ __forceinline__ unsigned sw128(unsigned off)
{
    return off ^ ((off >> 3) & 0x70);
}
__device__ __forceinline__ unsigned pack_bf2(float lo, float hi)
{
    unsigned r;
    asm("cvt.rn.bf16x2.f32 %0, %1, %2;" : "=r"(r) : "f"(hi), "f"(lo));
    return r;
}
__device__ __forceinline__ unsigned pack_resid(float lo, float hi, unsigned hp)
{
    float hl = __uint_as_float(hp << 16);
    float hh = __uint_as_float(hp & 0xFFFF0000u);
    return pack_bf2(lo - hl, hi - hh);
}
__device__ __forceinline__ void ldsm4(unsigned* r, unsigned addr)
{
    asm volatile("ldmatrix.sync.aligned.m8n8.x4.shared.b16 {%0,%1,%2,%3}, [%4];"
                 : "=r"(r[0]), "=r"(r[1]), "=r"(r[2]), "=r"(r[3]) : "r"(addr));
}
__device__ __forceinline__ void ldsm4t(unsigned* r, unsigned addr)
{
    asm volatile("ldmatrix.sync.aligned.m8n8.x4.trans.shared.b16 {%0,%1,%2,%3}, [%4];"
                 : "=r"(r[0]), "=r"(r[1]), "=r"(r[2]), "=r"(r[3]) : "r"(addr));
}
__device__ __forceinline__ void mma16816(float* c, const unsigned* a,
                                         const unsigned* b)
{
    asm volatile(
        "mma.sync.aligned.m16n8k16.row.col.f32.bf16.bf16.f32 "
        "{%0,%1,%2,%3}, {%4,%5,%6,%7}, {%8,%9}, {%0,%1,%2,%3};"
        : "+f"(c[0]), "+f"(c[1]), "+f"(c[2]), "+f"(c[3])
        : "r"(a[0]), "r"(a[1]), "r"(a[2]), "r"(a[3]), "r"(b[0]), "r"(b[1]));
}
__device__ __forceinline__ void cp16(unsigned dst, const void* src)
{
    asm volatile("cp.async.cg.shared.global [%0], [%1], 16;"
                 :: "r"(dst), "l"(src) : "memory");
}
__device__ __forceinline__ void cp_commit()
{
    asm volatile("cp.async.commit_group;" ::: "memory");
}
template <int N>
__device__ __forceinline__ void cp_wait()
{
    asm volatile("cp.async.wait_group %0;" :: "n"(N) : "memory");
}

// ---------------------------------------------------------------------------
// Prep: l2norm Q,K rows -> bf16 hi/lo; vm = V*mask -> fp32 + bf16 hi/lo
// ---------------------------------------------------------------------------
__global__ void __launch_bounds__(256) yoso_prep(
    const float* __restrict__ Q, const float* __restrict__ K,
    const float* __restrict__ V, const float* __restrict__ mask)
{
    int r = blockIdx.x * 8 + threadIdx.y;
    int lane = threadIdx.x;
    int s = r % SS;
    int b = r / (HH * SS);
    float m = mask[b * SS + s];
    size_t off = (size_t)r * DD;
    size_t uoff = (size_t)r * 32 + lane;

    {
        float2 v = *(const float2*)(Q + off + lane * 2);
        float sq = v.x * v.x + v.y * v.y;
        sq += __shfl_xor_sync(0xffffffff, sq, 16);
        sq += __shfl_xor_sync(0xffffffff, sq, 8);
        sq += __shfl_xor_sync(0xffffffff, sq, 4);
        sq += __shfl_xor_sync(0xffffffff, sq, 2);
        sq += __shfl_xor_sync(0xffffffff, sq, 1);
        float inv = 1.0f / fmaxf(sqrtf(sq), 1e-12f);
        float a0 = v.x * inv;
        float a1 = v.y * inv;
        unsigned hp = pack_bf2(a0, a1);
        ((unsigned*)g_qh)[uoff] = hp;
        ((unsigned*)g_ql)[uoff] = pack_resid(a0, a1, hp);
    }
    {
        float2 v = *(const float2*)(K + off + lane * 2);
        float sq = v.x * v.x + v.y * v.y;
        sq += __shfl_xor_sync(0xffffffff, sq, 16);
        sq += __shfl_xor_sync(0xffffffff, sq, 8);
        sq += __shfl_xor_sync(0xffffffff, sq, 4);
        sq += __shfl_xor_sync(0xffffffff, sq, 2);
        sq += __shfl_xor_sync(0xffffffff, sq, 1);
        float inv = 1.0f / fmaxf(sqrtf(sq), 1e-12f);
        float a0 = v.x * inv;
        float a1 = v.y * inv;
        unsigned hp = pack_bf2(a0, a1);
        ((unsigned*)g_kh)[uoff] = hp;
        ((unsigned*)g_kl)[uoff] = pack_resid(a0, a1, hp);
    }
    {
        float2 v = *(const float2*)(V + off + lane * 2);
        float o0 = v.x * m;
        float o1 = v.y * m;
        float2 o;
        o.x = o0;
        o.y = o1;
        *(float2*)(g_vm + off + lane * 2) = o;
        unsigned hp = pack_bf2(o0, o1);
        ((unsigned*)g_vh)[uoff] = hp;
        ((unsigned*)g_vl)[uoff] = pack_resid(o0, o1, hp);
    }
}

// ---------------------------------------------------------------------------
// Fast branchless W(x) = (1 - acos(x)/pi)^8
// ---------------------------------------------------------------------------
__device__ __forceinline__ float yoso_w(float x)
{
    x = fminf(fmaxf(x, -1.0f), 1.0f);
    float ax = fabsf(x);
    float p = -0.0012624911f;
    p = fmaf(p, ax,  0.0066700901f);
    p = fmaf(p, ax, -0.0170881256f);
    p = fmaf(p, ax,  0.0308918810f);
    p = fmaf(p, ax, -0.0501743046f);
    p = fmaf(p, ax,  0.0889789874f);
    p = fmaf(p, ax, -0.2145988016f);
    p = fmaf(p, ax,  1.5707963050f);
    float s;
    asm("sqrt.approx.f32 %0, %1;" : "=f"(s) : "f"(1.0f - ax));
    float u = s * p * 0.31830988618379067f;
    float t = (x >= 0.0f) ? (1.0f - u) : u;
    float t2 = t * t;
    float t4 = t2 * t2;
    return t4 * t4;
}

// ---------------------------------------------------------------------------
// Main kernel: mma.sync bf16 split GEMMs + cp.async pipeline.
// Block 128 threads / 64 query rows; 64-key tiles. W stays in registers.
// smem: QH QL | K stage0 (H,L) | K stage1 (H,L) | VH VL   (8KB each, 64KB)
// ---------------------------------------------------------------------------
#define SM_QH  0
#define SM_QL  8192
#define SM_K0H 16384
#define SM_K0L 24576
#define SM_K1H 32768
#define SM_K1L 40960
#define SM_VH  49152
#define SM_VL  57344
#define SMEM_BYTES 65536

// async-copy one 64x64 bf16 tile (row-major, 128B smem rows, SW128 swizzle)
__device__ __forceinline__ void cp_tile64(
    unsigned dst, const __nv_bfloat16* g, int tid)
{
    #pragma unroll
    for (int i = 0; i < 4; ++i) {
        int c = tid + i * 128;
        int row = c >> 3;
        int col = c & 7;
        cp16(dst + sw128((unsigned)(row * 128 + col * 16)),
             g + (size_t)row * DD + col * 8);
    }
}

__global__ void __launch_bounds__(128, 3) yoso_mma(
    const float* __restrict__ mask, const float* __restrict__ convw,
    float* __restrict__ out)
{
    extern __shared__ char smc[];
    const int tid = threadIdx.x;
    const int wid = tid >> 5;
    const int lane = tid & 31;
    const int bh = blockIdx.y;
    const int h = bh % HH;
    const int b = bh / HH;
    const int row0 = blockIdx.x * 64;
    const size_t base = (size_t)bh * SS * DD;
    const unsigned smb = smem_u32(smc);

    // prologue: async-load Q (hi/lo) and K tile 0 into stage 0
    cp_tile64(smb + SM_QH, g_qh + base + (size_t)row0 * DD, tid);
    cp_tile64(smb + SM_QL, g_ql + base + (size_t)row0 * DD, tid);
    cp_tile64(smb + SM_K0H, g_kh + base, tid);
    cp_tile64(smb + SM_K0L, g_kl + base, tid);
    cp_commit();

    // ldmatrix lane offsets
    const int mm = lane >> 3;
    const int r8 = lane & 7;
    const unsigned aOff = (unsigned)((16 * wid + (mm & 1) * 8 + r8) * 128
                                     + 16 * (mm >> 1));
    const int kRow = r8 + 8 * (mm >> 1);
    const int kCol = 16 * (mm & 1);
    const int vRow = r8 + 8 * (mm & 1);
    const int vCol = 16 * (mm >> 1);

    float acc[8][4];
    #pragma unroll
    for (int j = 0; j < 8; ++j) {
        #pragma unroll
        for (int i = 0; i < 4; ++i) {
            acc[j][i] = 0.0f;
        }
    }

    for (int kt = 0; kt < SS / 64; ++kt) {
        const int kbase = kt * 64;
        const unsigned kcur = (kt & 1) ? SM_K1H : SM_K0H;
        const unsigned knxt = (kt & 1) ? SM_K0H : SM_K1H;

        // K(kt) (and on kt==0 also Q) are complete; all prior V reads done.
        cp_wait<0>();
        __syncthreads();

        // issue V(kt)  [group B]
        cp_tile64(smb + SM_VH, g_vh + base + (size_t)kbase * DD, tid);
        cp_tile64(smb + SM_VL, g_vl + base + (size_t)kbase * DD, tid);
        cp_commit();
        // issue K(kt+1) into the other stage  [group A]
        {
            const int kb2 = ((kt + 1) & 31) * 64;
            cp_tile64(smb + knxt, g_kh + base + (size_t)kb2 * DD, tid);
            cp_tile64(smb + knxt + 8192, g_kl + base + (size_t)kb2 * DD, tid);
            cp_commit();
        }

        // ---- GEMM1: dots = Q*K^T (3 split products) ----
        float dts[8][4];
        #pragma unroll
        for (int j = 0; j < 8; ++j) {
            #pragma unroll
            for (int i = 0; i < 4; ++i) {
                dts[j][i] = 0.0f;
            }
        }
        #pragma unroll
        for (int t = 0; t < 4; ++t) {
            unsigned aH[4];
            unsigned aL[4];
            ldsm4(aH, smb + SM_QH + sw128(aOff + 32 * t));
            ldsm4(aL, smb + SM_QL + sw128(aOff + 32 * t));
            #pragma unroll
            for (int u = 0; u < 4; ++u) {
                unsigned bHf[4];
                unsigned bLf[4];
                unsigned off = sw128((unsigned)((16 * u + kRow) * 128
                                                + 32 * t + kCol));
                ldsm4(bHf, smb + kcur + off);
                ldsm4(bLf, smb + kcur + 8192 + off);
                mma16816(dts[2 * u],     aH, bHf);
                mma16816(dts[2 * u + 1], aH, bHf + 2);
                mma16816(dts[2 * u],     aH, bLf);
                mma16816(dts[2 * u + 1], aH, bLf + 2);
                mma16816(dts[2 * u],     aL, bHf);
                mma16816(dts[2 * u + 1], aL, bHf + 2);
            }
        }

        // ---- transform: W = yoso_w(dots), hi/lo bf16 A-fragments ----
        unsigned wh[4][4];
        unsigned wl[4][4];
        #pragma unroll
        for (int t = 0; t < 4; ++t) {
            #pragma unroll
            for (int q2 = 0; q2 < 4; ++q2) {
                int j = 2 * t + (q2 >> 1);
                int g = q2 & 1;
                float f0 = yoso_w(dts[j][2 * g]);
                float f1 = yoso_w(dts[j][2 * g + 1]);
                unsigned hp = pack_bf2(f0, f1);
                wh[t][q2] = hp;
                wl[t][q2] = pack_resid(f0, f1, hp);
            }
        }

        // V(kt) complete (group A may still be in flight)
        cp_wait<1>();
        __syncthreads();

        // ---- GEMM2: acc += W * V (3 split products) ----
        #pragma unroll
        for (int t = 0; t < 4; ++t) {
            #pragma unroll
            for (int u = 0; u < 4; ++u) {
                unsigned vHf[4];
                unsigned vLf[4];
                unsigned off = sw128((unsigned)((16 * t + vRow) * 128
                                                + 32 * u + vCol));
                ldsm4t(vHf, smb + SM_VH + off);
                ldsm4t(vLf, smb + SM_VL + off);
                mma16816(acc[2 * u],     wh[t], vHf);
                mma16816(acc[2 * u + 1], wh[t], vHf + 2);
                mma16816(acc[2 * u],     wh[t], vLf);
                mma16816(acc[2 * u + 1], wh[t], vLf + 2);
                mma16816(acc[2 * u],     wl[t], vHf);
                mma16816(acc[2 * u + 1], wl[t], vHf + 2);
            }
        }
    }

    // ---- epilogue ----
    const int quad = lane >> 2;
    const int qi = lane & 3;
    const int r1 = row0 + 16 * wid + quad;
    const int r2 = r1 + 8;
    const float mq1 = mask[b * SS + r1];
    const float mq2 = mask[b * SS + r2];

    float ss1 = 0.0f;
    float ss2 = 0.0f;
    #pragma unroll
    for (int j = 0; j < 8; ++j) {
        ss1 = fmaf(acc[j][0], acc[j][0], ss1);
        ss1 = fmaf(acc[j][1], acc[j][1], ss1);
        ss2 = fmaf(acc[j][2], acc[j][2], ss2);
        ss2 = fmaf(acc[j][3], acc[j][3], ss2);
    }
    ss1 += __shfl_xor_sync(0xffffffff, ss1, 1);
    ss1 += __shfl_xor_sync(0xffffffff, ss1, 2);
    ss2 += __shfl_xor_sync(0xffffffff, ss2, 1);
    ss2 += __shfl_xor_sync(0xffffffff, ss2, 2);
    const float s1 = mq1 / fmaxf(mq1 * sqrtf(ss1), 1e-12f);
    const float s2 = mq2 / fmaxf(mq2 * sqrtf(ss2), 1e-12f);

    const float w0 = convw[h * 3 + 0];
    const float w1 = convw[h * 3 + 1];
    const float w2 = convw[h * 3 + 2];

    #pragma unroll
    for (int j = 0; j < 8; ++j) {
        const int col = 8 * j + qi * 2;
        {
            const float* vp = g_vm + base + (size_t)r1 * DD + col;
            float2 c1 = *(const float2*)vp;
            float2 c0;
            c0.x = 0.0f;
            c0.y = 0.0f;
            if (r1 > 0) {
                c0 = *(const float2*)(vp - DD);
            }
            float2 c2 = *(const float2*)(vp + DD);   // r1 <= 2039, safe
            float2 o;
            o.x = fmaf(acc[j][0], s1, w0 * c0.x + w1 * c1.x + w2 * c2.x);
            o.y = fmaf(acc[j][1], s1, w0 * c0.y + w1 * c1.y + w2 * c2.y);
            *(float2*)(out + base + (size_t)r1 * DD + col) = o;
        }
        {
            const float* vp = g_vm + base + (size_t)r2 * DD + col;
            float2 c1 = *(const float2*)vp;
            float2 c0 = *(const float2*)(vp - DD);   // r2 >= 8, safe
            float2 c2;
            c2.x = 0.0f;
            c2.y = 0.0f;
            if (r2 < SS - 1) {
                c2 = *(const float2*)(vp + DD);
            }
            float2 o;
            o.x = fmaf(acc[j][2], s2, w0 * c0.x + w1 * c1.x + w2 * c2.x);
            o.y = fmaf(acc[j][3], s2, w0 * c0.y + w1 * c1.y + w2 * c2.y);
            *(float2*)(out + base + (size_t)r2 * DD + col) = o;
        }
    }
}

// ---------------------------------------------------------------------------
extern "C" void kernel_launch(void* const* d_in, const int* in_sizes, int n_in,
                              void* d_out, int out_size)
{
    const float* Q     = (const float*)d_in[0];
    const float* K     = (const float*)d_in[1];
    const float* V     = (const float*)d_in[2];
    const float* mask  = (const float*)d_in[3];
    const float* convw = (const float*)d_in[4];
    float* out = (float*)d_out;

    yoso_prep<<<NROWS / 8, dim3(32, 8)>>>(Q, K, V, mask);

    cudaFuncSetAttribute(yoso_mma, cudaFuncAttributeMaxDynamicSharedMemorySize,
                         SMEM_BYTES);
    dim3 grid(SS / 64, BH);
    yoso_mma<<<grid, 128, SMEM_BYTES>>>(mask, convw, out);
}